// round 2
// baseline (speedup 1.0000x reference)
#include <cuda_runtime.h>
#include <cstdint>

#define E_TOTAL  1000000
#define NN       100000
#define HDIM     128

// Precomputed P = emb @ [W1_top | W1_bot]  : [NN, 1024] fp32.
// P[n, 0:512]   = emb[n] @ W1[0:128, :]
// P[n, 512:1024]= emb[n] @ W1[128:256, :]
__device__ float g_P[(size_t)NN * 1024];

__device__ __forceinline__ uint32_t f2tf32(float f) {
    uint32_t r;
    asm("cvt.rna.tf32.f32 %0, %1;" : "=r"(r) : "f"(f));
    return r;
}

__device__ __forceinline__ void mma_tf32(float* d, const uint32_t* a, const uint32_t* b) {
    asm volatile(
        "mma.sync.aligned.m16n8k8.row.col.f32.tf32.tf32.f32 "
        "{%0,%1,%2,%3}, {%4,%5,%6,%7}, {%8,%9}, {%0,%1,%2,%3};\n"
        : "+f"(d[0]), "+f"(d[1]), "+f"(d[2]), "+f"(d[3])
        : "r"(a[0]), "r"(a[1]), "r"(a[2]), "r"(a[3]),
          "r"(b[0]), "r"(b[1]));
}

// ============================================================================
// Kernel 1: P = emb @ Wcat   ([NN,128] x [128,1024])
// grid (1563, 8), block 128 (4 warps). Each block: 64 rows x 128 cols, K=128.
// ============================================================================
#define PRE_ASTR 132   // 64 x 132 floats (pad: bank = laneid, conflict-free)
#define PRE_BSTR 136   // 128 x 136 floats
#define PRE_SMEM (64*PRE_ASTR*4 + 128*PRE_BSTR*4)

__global__ __launch_bounds__(128) void precompute_kernel(
    const float* __restrict__ emb, const float* __restrict__ W1)
{
    extern __shared__ char smem[];
    float* As = (float*)smem;                        // [64][PRE_ASTR]
    float* Bs = (float*)(smem + 64 * PRE_ASTR * 4);  // [128][PRE_BSTR]

    const int tid  = threadIdx.x;
    const int warp = tid >> 5;
    const int lane = tid & 31;
    const int row0 = blockIdx.x * 64;
    const int nblk = blockIdx.y;           // output cols nblk*128 ..

    // Load A tile: emb[row0 .. row0+63][0:128] (tf32-converted)
    #pragma unroll
    for (int i = 0; i < 16; i++) {
        int flat = (i * 128 + tid) * 4;    // 0..32764
        int r = flat >> 7;
        int c = flat & 127;
        float4 v = make_float4(0.f, 0.f, 0.f, 0.f);
        int node = row0 + r;
        if (node < NN) v = *(const float4*)(emb + (size_t)node * HDIM + c);
        float* dst = As + r * PRE_ASTR + c;
        dst[0] = __uint_as_float(f2tf32(v.x));
        dst[1] = __uint_as_float(f2tf32(v.y));
        dst[2] = __uint_as_float(f2tf32(v.z));
        dst[3] = __uint_as_float(f2tf32(v.w));
    }
    // Load B tile: Wcat[k][nblk*128 + c], k = 0..127
    #pragma unroll
    for (int i = 0; i < 32; i++) {
        int flat = (i * 128 + tid) * 4;    // 0..65532
        int k = flat >> 7;
        int c = flat & 127;
        int j = nblk * 128 + c;
        const float* src = (j < 512) ? (W1 + (size_t)k * 512 + j)
                                     : (W1 + (size_t)(128 + k) * 512 + (j - 512));
        float4 v = *(const float4*)src;
        float* dst = Bs + k * PRE_BSTR + c;
        dst[0] = __uint_as_float(f2tf32(v.x));
        dst[1] = __uint_as_float(f2tf32(v.y));
        dst[2] = __uint_as_float(f2tf32(v.z));
        dst[3] = __uint_as_float(f2tf32(v.w));
    }
    __syncthreads();

    float acc[16][4];
    #pragma unroll
    for (int nt = 0; nt < 16; nt++)
        #pragma unroll
        for (int j = 0; j < 4; j++) acc[nt][j] = 0.f;

    const int arow = warp * 16 + (lane >> 2);
    const int q    = lane & 3;
    #pragma unroll
    for (int kt = 0; kt < 16; kt++) {
        uint32_t a[4];
        const float* ap = As + arow * PRE_ASTR + kt * 8 + q;
        a[0] = __float_as_uint(ap[0]);
        a[1] = __float_as_uint(ap[8 * PRE_ASTR]);
        a[2] = __float_as_uint(ap[4]);
        a[3] = __float_as_uint(ap[8 * PRE_ASTR + 4]);
        #pragma unroll
        for (int nt = 0; nt < 16; nt++) {
            const float* bp = Bs + (kt * 8 + q) * PRE_BSTR + nt * 8 + (lane >> 2);
            uint32_t b[2];
            b[0] = __float_as_uint(bp[0]);
            b[1] = __float_as_uint(bp[4 * PRE_BSTR]);
            mma_tf32(acc[nt], a, b);
        }
    }

    const int r0 = row0 + warp * 16 + (lane >> 2);
    const int r1 = r0 + 8;
    const int cb = nblk * 128 + q * 2;
    #pragma unroll
    for (int nt = 0; nt < 16; nt++) {
        int c = cb + nt * 8;
        if (r0 < NN) *(float2*)(g_P + (size_t)r0 * 1024 + c) = make_float2(acc[nt][0], acc[nt][1]);
        if (r1 < NN) *(float2*)(g_P + (size_t)r1 * 1024 + c) = make_float2(acc[nt][2], acc[nt][3]);
    }
}

// ============================================================================
// Kernel 2: per-edge  h1 = relu(P[col,0:512] + P[row,512:1024] + b1)
//           h2 = relu(h1 @ W2 + b2);  out = sigmoid(h2 @ W3 + b3)
// grid 7813, block 256 (8 warps). Tile: 128 edges; K=512 in 8 chunks of 64.
// ============================================================================
#define EK_HSTR 68    // 128 x 68 floats  (bank = laneid for A-frag loads)
#define EK_WSTR 136   // 64 x 136 floats
#define EK_SMEM (128*EK_HSTR*4 + 64*EK_WSTR*4 + 256*4 + 256*4)

__global__ __launch_bounds__(256) void edge_kernel(
    const int* __restrict__ ei,
    const float* __restrict__ b1, const float* __restrict__ W2,
    const float* __restrict__ b2, const float* __restrict__ W3,
    const float* __restrict__ b3, float* __restrict__ out)
{
    extern __shared__ char smem[];
    float* Hs   = (float*)smem;                                   // [128][EK_HSTR]
    float* Ws   = (float*)(smem + 128 * EK_HSTR * 4);             // [64][EK_WSTR]
    int*   colS = (int*)  (smem + 128 * EK_HSTR * 4 + 64 * EK_WSTR * 4); // [128]
    int*   rowS = colS + 128;                                     // [128]
    float* b2s  = (float*)(rowS + 128);                           // [128]
    float* w3s  = b2s + 128;                                      // [128]

    const int tid  = threadIdx.x;
    const int warp = tid >> 5;
    const int lane = tid & 31;
    const int e0   = blockIdx.x * 128;

    if (tid < 128) {
        int eg = e0 + tid;
        int c = 0, r = 0;
        if (eg < E_TOTAL) { c = ei[eg]; r = ei[E_TOTAL + eg]; }
        colS[tid] = c; rowS[tid] = r;
        b2s[tid] = b2[tid];
        w3s[tid] = W3[tid];
    }
    __syncthreads();

    const int eL = tid >> 1;          // edge-in-tile this thread gathers for
    const int kh = (tid & 1) * 32;    // which 32-float half of the 64-chunk
    const size_t aoff = (size_t)colS[eL] * 1024 + kh;          // P[col][0:512]
    const size_t boff = (size_t)rowS[eL] * 1024 + 512 + kh;    // P[row][512:1024]

    float acc[16][4];
    #pragma unroll
    for (int nt = 0; nt < 16; nt++)
        #pragma unroll
        for (int j = 0; j < 4; j++) acc[nt][j] = 0.f;

    const int arow = warp * 16 + (lane >> 2);
    const int q    = lane & 3;

    for (int kc = 0; kc < 8; kc++) {
        __syncthreads();   // previous iter's mma reads done before overwrite
        // ---- gather + fused add-bias-relu -> Hs (tf32) ----
        {
            const float* pa  = g_P + aoff + kc * 64;
            const float* pb  = g_P + boff + kc * 64;
            const float* pb1 = b1 + kc * 64 + kh;
            float* dst = Hs + eL * EK_HSTR + kh;
            #pragma unroll
            for (int i = 0; i < 8; i++) {
                float4 va = *(const float4*)(pa  + i * 4);
                float4 vb = *(const float4*)(pb  + i * 4);
                float4 vc = *(const float4*)(pb1 + i * 4);
                dst[i*4+0] = __uint_as_float(f2tf32(fmaxf(va.x + vb.x + vc.x, 0.f)));
                dst[i*4+1] = __uint_as_float(f2tf32(fmaxf(va.y + vb.y + vc.y, 0.f)));
                dst[i*4+2] = __uint_as_float(f2tf32(fmaxf(va.z + vb.z + vc.z, 0.f)));
                dst[i*4+3] = __uint_as_float(f2tf32(fmaxf(va.w + vb.w + vc.w, 0.f)));
            }
        }
        // ---- stage W2 chunk [64 x 128] -> Ws (tf32) ----
        #pragma unroll
        for (int i = 0; i < 8; i++) {
            int flat = (i * 256 + tid) * 4;   // 0..8188
            int k = flat >> 7;
            int c = flat & 127;
            float4 v = *(const float4*)(W2 + (size_t)(kc * 64 + k) * 128 + c);
            float* dst = Ws + k * EK_WSTR + c;
            dst[0] = __uint_as_float(f2tf32(v.x));
            dst[1] = __uint_as_float(f2tf32(v.y));
            dst[2] = __uint_as_float(f2tf32(v.z));
            dst[3] = __uint_as_float(f2tf32(v.w));
        }
        __syncthreads();
        // ---- mma: [16 x 128] per warp over this 64-K chunk ----
        #pragma unroll
        for (int kt = 0; kt < 8; kt++) {
            uint32_t a[4];
            const float* ap = Hs + arow * EK_HSTR + kt * 8 + q;
            a[0] = __float_as_uint(ap[0]);
            a[1] = __float_as_uint(ap[8 * EK_HSTR]);
            a[2] = __float_as_uint(ap[4]);
            a[3] = __float_as_uint(ap[8 * EK_HSTR + 4]);
            #pragma unroll
            for (int nt = 0; nt < 16; nt++) {
                const float* bp = Ws + (kt * 8 + q) * EK_WSTR + nt * 8 + (lane >> 2);
                uint32_t b[2];
                b[0] = __float_as_uint(bp[0]);
                b[1] = __float_as_uint(bp[4 * EK_WSTR]);
                mma_tf32(acc[nt], a, b);
            }
        }
    }

    // ---- epilogue: relu(+b2), dot W3, +b3, sigmoid ----
    float p0 = 0.f, p1 = 0.f;
    #pragma unroll
    for (int nt = 0; nt < 16; nt++) {
        int c = nt * 8 + q * 2;
        float w0 = w3s[c], w1 = w3s[c + 1];
        float g0 = b2s[c], g1 = b2s[c + 1];
        p0 += fmaxf(acc[nt][0] + g0, 0.f) * w0 + fmaxf(acc[nt][1] + g1, 0.f) * w1;
        p1 += fmaxf(acc[nt][2] + g0, 0.f) * w0 + fmaxf(acc[nt][3] + g1, 0.f) * w1;
    }
    p0 += __shfl_xor_sync(0xffffffffu, p0, 1);
    p0 += __shfl_xor_sync(0xffffffffu, p0, 2);
    p1 += __shfl_xor_sync(0xffffffffu, p1, 1);
    p1 += __shfl_xor_sync(0xffffffffu, p1, 2);

    if (q == 0) {
        float bb = b3[0];
        int r0 = e0 + warp * 16 + (lane >> 2);
        int r1 = r0 + 8;
        if (r0 < E_TOTAL) out[r0] = 1.f / (1.f + expf(-(p0 + bb)));
        if (r1 < E_TOTAL) out[r1] = 1.f / (1.f + expf(-(p1 + bb)));
    }
}

// ============================================================================
extern "C" void kernel_launch(void* const* d_in, const int* in_sizes, int n_in,
                              void* d_out, int out_size)
{
    const float* emb = (const float*)d_in[0];
    const int*   ei  = (const int*)d_in[1];
    const float* W1  = (const float*)d_in[2];
    const float* b1  = (const float*)d_in[3];
    const float* W2  = (const float*)d_in[4];
    const float* b2  = (const float*)d_in[5];
    const float* W3  = (const float*)d_in[6];
    const float* b3  = (const float*)d_in[7];
    float* out = (float*)d_out;

    cudaFuncSetAttribute(precompute_kernel,
                         cudaFuncAttributeMaxDynamicSharedMemorySize, PRE_SMEM);
    cudaFuncSetAttribute(edge_kernel,
                         cudaFuncAttributeMaxDynamicSharedMemorySize, EK_SMEM);

    precompute_kernel<<<dim3(1563, 8), 128, PRE_SMEM>>>(emb, W1);
    edge_kernel<<<7813, 256, EK_SMEM>>>(ei, b1, W2, b2, W3, b3, out);
}

// round 3
// speedup vs baseline: 2.1832x; 2.1832x over previous
#include <cuda_runtime.h>
#include <cuda_fp16.h>
#include <cstdint>

#define E_TOTAL  1000000
#define NN       100000
#define HDIM     128

// P = emb @ [W1_top | W1_bot] stored fp16 : [NN][1024]
__device__ __half g_Ph[(size_t)NN * 1024];
// W2 transposed, fp16 : [128 n][512 k]
__device__ __half g_W2T[(size_t)128 * 512];

__device__ __forceinline__ uint32_t f2tf32(float f) {
    uint32_t r;
    asm("cvt.rna.tf32.f32 %0, %1;" : "=r"(r) : "f"(f));
    return r;
}

__device__ __forceinline__ void mma_tf32(float* d, const uint32_t* a, const uint32_t* b) {
    asm volatile(
        "mma.sync.aligned.m16n8k8.row.col.f32.tf32.tf32.f32 "
        "{%0,%1,%2,%3}, {%4,%5,%6,%7}, {%8,%9}, {%0,%1,%2,%3};\n"
        : "+f"(d[0]), "+f"(d[1]), "+f"(d[2]), "+f"(d[3])
        : "r"(a[0]), "r"(a[1]), "r"(a[2]), "r"(a[3]),
          "r"(b[0]), "r"(b[1]));
}

__device__ __forceinline__ void mma_f16(float* d, const uint32_t* a, const uint32_t* b) {
    asm volatile(
        "mma.sync.aligned.m16n8k16.row.col.f32.f16.f16.f32 "
        "{%0,%1,%2,%3}, {%4,%5,%6,%7}, {%8,%9}, {%0,%1,%2,%3};\n"
        : "+f"(d[0]), "+f"(d[1]), "+f"(d[2]), "+f"(d[3])
        : "r"(a[0]), "r"(a[1]), "r"(a[2]), "r"(a[3]),
          "r"(b[0]), "r"(b[1]));
}

__device__ __forceinline__ float2 h2f(uint32_t w) {
    __half2 h = *reinterpret_cast<__half2*>(&w);
    return __half22float2(h);
}
__device__ __forceinline__ uint32_t f2h2(float lo, float hi) {
    __half2 p = __floats2half2_rn(lo, hi);
    return *reinterpret_cast<uint32_t*>(&p);
}

// ============================================================================
// Kernel 0: transpose W2 [512][128] fp32 -> g_W2T [128][512] fp16
// ============================================================================
__global__ __launch_bounds__(256) void transpose_w2_kernel(const float* __restrict__ W2)
{
    int idx = blockIdx.x * 256 + threadIdx.x;   // 0..65535
    int k = idx >> 7;          // 0..511
    int n = idx & 127;         // 0..127  (coalesced read)
    float v = W2[(size_t)k * 128 + n];
    g_W2T[(size_t)n * 512 + k] = __float2half_rn(v);
}

// ============================================================================
// Kernel 1: P = emb @ Wcat   ([NN,128] x [128,1024]) -> fp16
// grid (1563, 8), block 128.
// ============================================================================
#define PRE_ASTR 132
#define PRE_BSTR 136
#define PRE_SMEM (64*PRE_ASTR*4 + 128*PRE_BSTR*4)

__global__ __launch_bounds__(128) void precompute_kernel(
    const float* __restrict__ emb, const float* __restrict__ W1)
{
    extern __shared__ char smem[];
    float* As = (float*)smem;                        // [64][PRE_ASTR]
    float* Bs = (float*)(smem + 64 * PRE_ASTR * 4);  // [128][PRE_BSTR]

    const int tid  = threadIdx.x;
    const int warp = tid >> 5;
    const int lane = tid & 31;
    const int row0 = blockIdx.x * 64;
    const int nblk = blockIdx.y;

    #pragma unroll
    for (int i = 0; i < 16; i++) {
        int flat = (i * 128 + tid) * 4;
        int r = flat >> 7;
        int c = flat & 127;
        float4 v = make_float4(0.f, 0.f, 0.f, 0.f);
        int node = row0 + r;
        if (node < NN) v = *(const float4*)(emb + (size_t)node * HDIM + c);
        float* dst = As + r * PRE_ASTR + c;
        dst[0] = __uint_as_float(f2tf32(v.x));
        dst[1] = __uint_as_float(f2tf32(v.y));
        dst[2] = __uint_as_float(f2tf32(v.z));
        dst[3] = __uint_as_float(f2tf32(v.w));
    }
    #pragma unroll
    for (int i = 0; i < 32; i++) {
        int flat = (i * 128 + tid) * 4;
        int k = flat >> 7;
        int c = flat & 127;
        int j = nblk * 128 + c;
        const float* src = (j < 512) ? (W1 + (size_t)k * 512 + j)
                                     : (W1 + (size_t)(128 + k) * 512 + (j - 512));
        float4 v = *(const float4*)src;
        float* dst = Bs + k * PRE_BSTR + c;
        dst[0] = __uint_as_float(f2tf32(v.x));
        dst[1] = __uint_as_float(f2tf32(v.y));
        dst[2] = __uint_as_float(f2tf32(v.z));
        dst[3] = __uint_as_float(f2tf32(v.w));
    }
    __syncthreads();

    float acc[16][4];
    #pragma unroll
    for (int nt = 0; nt < 16; nt++)
        #pragma unroll
        for (int j = 0; j < 4; j++) acc[nt][j] = 0.f;

    const int arow = warp * 16 + (lane >> 2);
    const int q    = lane & 3;
    #pragma unroll
    for (int kt = 0; kt < 16; kt++) {
        uint32_t a[4];
        const float* ap = As + arow * PRE_ASTR + kt * 8 + q;
        a[0] = __float_as_uint(ap[0]);
        a[1] = __float_as_uint(ap[8 * PRE_ASTR]);
        a[2] = __float_as_uint(ap[4]);
        a[3] = __float_as_uint(ap[8 * PRE_ASTR + 4]);
        #pragma unroll
        for (int nt = 0; nt < 16; nt++) {
            const float* bp = Bs + (kt * 8 + q) * PRE_BSTR + nt * 8 + (lane >> 2);
            uint32_t b[2];
            b[0] = __float_as_uint(bp[0]);
            b[1] = __float_as_uint(bp[4 * PRE_BSTR]);
            mma_tf32(acc[nt], a, b);
        }
    }

    const int r0 = row0 + warp * 16 + (lane >> 2);
    const int r1 = r0 + 8;
    const int cb = nblk * 128 + q * 2;
    #pragma unroll
    for (int nt = 0; nt < 16; nt++) {
        int c = cb + nt * 8;     // even
        if (r0 < NN)
            *(uint32_t*)(g_Ph + (size_t)r0 * 1024 + c) = f2h2(acc[nt][0], acc[nt][1]);
        if (r1 < NN)
            *(uint32_t*)(g_Ph + (size_t)r1 * 1024 + c) = f2h2(acc[nt][2], acc[nt][3]);
    }
}

// ============================================================================
// Kernel 2: edge MLP. Tile = 128 edges x 128 N, K = 512 in 8 chunks of 64.
// 8 warps as 2(M=64) x 4(N=32). fp16 m16n8k16 MMA.
// smem strides: 36 words/row (72 halfs) -> conflict-free STS.128 + frag LDS.
// ============================================================================
#define HS_STR 36   // uint32 words per row (64 halfs data + pad)

__global__ __launch_bounds__(256, 2) void edge_kernel(
    const int* __restrict__ ei,
    const float* __restrict__ b1,
    const float* __restrict__ b2, const float* __restrict__ W3,
    const float* __restrict__ b3, float* __restrict__ out)
{
    __shared__ uint32_t Hs[128 * HS_STR];   // h1 chunk, fp16 pairs
    __shared__ uint32_t Ws[128 * HS_STR];   // W2T chunk [n][k], fp16 pairs
    __shared__ float b1s[512];
    __shared__ float b2s[128];
    __shared__ float w3s[128];
    __shared__ float partS[4 * 128];
    __shared__ int   colS[128];
    __shared__ int   rowS[128];

    const int tid  = threadIdx.x;
    const int warp = tid >> 5;
    const int lane = tid & 31;
    const int q    = lane & 3;
    const int lr   = lane >> 2;          // 0..7
    const int wm   = warp >> 2;          // 0..1  (M group of 64 edges)
    const int wn   = warp & 3;           // 0..3  (N group of 32 cols)
    const int e0   = blockIdx.x * 128;

    if (tid < 128) {
        int eg = e0 + tid;
        int c = 0, r = 0;
        if (eg < E_TOTAL) { c = ei[eg]; r = ei[E_TOTAL + eg]; }
        colS[tid] = c; rowS[tid] = r;
        b2s[tid] = b2[tid];
        w3s[tid] = W3[tid];
    }
    b1s[tid]       = b1[tid];
    b1s[tid + 256] = b1[tid + 256];

    float acc[4][4][4];
    #pragma unroll
    for (int mt = 0; mt < 4; mt++)
        #pragma unroll
        for (int nt = 0; nt < 4; nt++)
            #pragma unroll
            for (int i = 0; i < 4; i++) acc[mt][nt][i] = 0.f;

    const int j = tid & 7;          // 16B segment within 128B row-chunk
    const int eg8 = tid >> 3;       // 0..31 base row per pass

    for (int kc = 0; kc < 8; kc++) {
        __syncthreads();
        // b1 slice for this thread's j (8 floats)
        float bv[8];
        {
            float4 t0 = *(const float4*)(b1s + kc * 64 + j * 8);
            float4 t1 = *(const float4*)(b1s + kc * 64 + j * 8 + 4);
            bv[0]=t0.x; bv[1]=t0.y; bv[2]=t0.z; bv[3]=t0.w;
            bv[4]=t1.x; bv[5]=t1.y; bv[6]=t1.z; bv[7]=t1.w;
        }
        // ---- gather + bias + relu -> Hs (fp16), 8 lanes x 16B per row ----
        #pragma unroll
        for (int pass = 0; pass < 4; pass++) {
            int e = pass * 32 + eg8;
            const uint4* pa = (const uint4*)(g_Ph + (size_t)colS[e] * 1024 + kc * 64 + j * 8);
            const uint4* pb = (const uint4*)(g_Ph + (size_t)rowS[e] * 1024 + 512 + kc * 64 + j * 8);
            uint4 va = *pa;
            uint4 vb = *pb;
            uint4 w;
            {
                float2 fa = h2f(va.x), fb = h2f(vb.x);
                w.x = f2h2(fmaxf(fa.x + fb.x + bv[0], 0.f), fmaxf(fa.y + fb.y + bv[1], 0.f));
            }
            {
                float2 fa = h2f(va.y), fb = h2f(vb.y);
                w.y = f2h2(fmaxf(fa.x + fb.x + bv[2], 0.f), fmaxf(fa.y + fb.y + bv[3], 0.f));
            }
            {
                float2 fa = h2f(va.z), fb = h2f(vb.z);
                w.z = f2h2(fmaxf(fa.x + fb.x + bv[4], 0.f), fmaxf(fa.y + fb.y + bv[5], 0.f));
            }
            {
                float2 fa = h2f(va.w), fb = h2f(vb.w);
                w.w = f2h2(fmaxf(fa.x + fb.x + bv[6], 0.f), fmaxf(fa.y + fb.y + bv[7], 0.f));
            }
            *(uint4*)(Hs + e * HS_STR + j * 4) = w;
        }
        // ---- stage W2T chunk [128 n][64 k] fp16 ----
        #pragma unroll
        for (int pass = 0; pass < 4; pass++) {
            int n = pass * 32 + eg8;
            uint4 v = *(const uint4*)(g_W2T + (size_t)n * 512 + kc * 64 + j * 8);
            *(uint4*)(Ws + n * HS_STR + j * 4) = v;
        }
        __syncthreads();
        // ---- mma over 4 k16 steps ----
        #pragma unroll
        for (int s = 0; s < 4; s++) {
            uint32_t bfr[4][2];
            #pragma unroll
            for (int nt = 0; nt < 4; nt++) {
                const uint32_t* bp = Ws + (wn * 32 + nt * 8 + lr) * HS_STR + q + 8 * s;
                bfr[nt][0] = bp[0];
                bfr[nt][1] = bp[4];
            }
            #pragma unroll
            for (int mt = 0; mt < 4; mt++) {
                const uint32_t* ap = Hs + (wm * 64 + mt * 16 + lr) * HS_STR + q + 8 * s;
                uint32_t a[4];
                a[0] = ap[0];
                a[1] = ap[8 * HS_STR];
                a[2] = ap[4];
                a[3] = ap[8 * HS_STR + 4];
                #pragma unroll
                for (int nt = 0; nt < 4; nt++)
                    mma_f16(acc[mt][nt], a, bfr[nt]);
            }
        }
    }

    // ---- epilogue: relu(+b2), partial dot with W3 per N-warp, reduce ----
    #pragma unroll
    for (int mt = 0; mt < 4; mt++) {
        float p0 = 0.f, p1 = 0.f;
        #pragma unroll
        for (int nt = 0; nt < 4; nt++) {
            int n = wn * 32 + nt * 8 + q * 2;
            float w0 = w3s[n], w1 = w3s[n + 1];
            float g0 = b2s[n], g1 = b2s[n + 1];
            p0 += fmaxf(acc[mt][nt][0] + g0, 0.f) * w0 + fmaxf(acc[mt][nt][1] + g1, 0.f) * w1;
            p1 += fmaxf(acc[mt][nt][2] + g0, 0.f) * w0 + fmaxf(acc[mt][nt][3] + g1, 0.f) * w1;
        }
        p0 += __shfl_xor_sync(0xffffffffu, p0, 1);
        p0 += __shfl_xor_sync(0xffffffffu, p0, 2);
        p1 += __shfl_xor_sync(0xffffffffu, p1, 1);
        p1 += __shfl_xor_sync(0xffffffffu, p1, 2);
        if (q == 0) {
            int rl = wm * 64 + mt * 16 + lr;
            partS[wn * 128 + rl]     = p0;
            partS[wn * 128 + rl + 8] = p1;
        }
    }
    __syncthreads();
    if (tid < 128) {
        float s = partS[tid] + partS[128 + tid] + partS[256 + tid] + partS[384 + tid] + b3[0];
        int eg = e0 + tid;
        if (eg < E_TOTAL) out[eg] = 1.f / (1.f + expf(-s));
    }
}

// ============================================================================
extern "C" void kernel_launch(void* const* d_in, const int* in_sizes, int n_in,
                              void* d_out, int out_size)
{
    const float* emb = (const float*)d_in[0];
    const int*   ei  = (const int*)d_in[1];
    const float* W1  = (const float*)d_in[2];
    const float* b1  = (const float*)d_in[3];
    const float* W2  = (const float*)d_in[4];
    const float* b2  = (const float*)d_in[5];
    const float* W3  = (const float*)d_in[6];
    const float* b3  = (const float*)d_in[7];
    float* out = (float*)d_out;

    cudaFuncSetAttribute(precompute_kernel,
                         cudaFuncAttributeMaxDynamicSharedMemorySize, PRE_SMEM);

    transpose_w2_kernel<<<256, 256>>>(W2);
    precompute_kernel<<<dim3(1563, 8), 128, PRE_SMEM>>>(emb, W1);
    edge_kernel<<<7813, 256>>>(ei, b1, b2, W3, b3, out);
}

// round 4
// speedup vs baseline: 3.3435x; 1.5315x over previous
#include <cuda_runtime.h>
#include <cuda_fp16.h>
#include <cstdint>

#define E_TOTAL  1000000
#define NN       100000
#define HDIM     128

// P = emb @ [W1_top | W1_bot] + (stored fp16) : [NN][1024]
__device__ __half g_Ph[(size_t)NN * 1024];
// W1 transposed fp16 : [1024 n][128 k]
__device__ __half g_W1T[(size_t)1024 * 128];
// W2 transposed fp16 : [128 n][512 k]
__device__ __half g_W2T[(size_t)128 * 512];

__device__ __forceinline__ void mma_f16(float* d, const uint32_t* a, const uint32_t* b) {
    asm volatile(
        "mma.sync.aligned.m16n8k16.row.col.f32.f16.f16.f32 "
        "{%0,%1,%2,%3}, {%4,%5,%6,%7}, {%8,%9}, {%0,%1,%2,%3};\n"
        : "+f"(d[0]), "+f"(d[1]), "+f"(d[2]), "+f"(d[3])
        : "r"(a[0]), "r"(a[1]), "r"(a[2]), "r"(a[3]),
          "r"(b[0]), "r"(b[1]));
}

__device__ __forceinline__ uint32_t f2h2(float lo, float hi) {
    __half2 p = __floats2half2_rn(lo, hi);
    return *reinterpret_cast<uint32_t*>(&p);
}
__device__ __forceinline__ __half2 u2h2(uint32_t w) {
    return *reinterpret_cast<__half2*>(&w);
}

__device__ __forceinline__ void cp16(uint32_t s, const void* g) {
    asm volatile("cp.async.cg.shared.global [%0], [%1], 16;\n" :: "r"(s), "l"(g));
}
__device__ __forceinline__ void cp_commit() {
    asm volatile("cp.async.commit_group;\n");
}
template <int N>
__device__ __forceinline__ void cp_wait() {
    asm volatile("cp.async.wait_group %0;\n" :: "n"(N));
}

// ============================================================================
// Kernel 0: prep — W1 -> g_W1T fp16 [1024][128]; W2 -> g_W2T fp16 [128][512]
// ============================================================================
__global__ __launch_bounds__(256) void prep_kernel(
    const float* __restrict__ W1, const float* __restrict__ W2)
{
    int bid = blockIdx.x;
    int tid = threadIdx.x;
    if (bid < 512) {                       // W1T: 131072 elems
        int idx = bid * 256 + tid;
        int k = idx >> 10;                 // 0..127
        int n = idx & 1023;                // 0..1023 (coalesced read)
        float v = (n < 512) ? W1[(size_t)k * 512 + n]
                            : W1[(size_t)(128 + k) * 512 + (n - 512)];
        g_W1T[(size_t)n * 128 + k] = __float2half_rn(v);
    } else {                               // W2T: 65536 elems
        int idx = (bid - 512) * 256 + tid;
        int k = idx >> 7;                  // 0..511
        int n = idx & 127;                 // coalesced read
        g_W2T[(size_t)n * 512 + k] = __float2half_rn(W2[(size_t)k * 128 + n]);
    }
}

// ============================================================================
// Kernel 1: P = emb @ Wcat -> fp16.  Tile 128 nodes x 128 cols, K=128.
// grid (782, 8), block 256 (8 warps: 2M x 4N). fp16 m16n8k16.
// ============================================================================
#define PC_STR 68   // uint32 words per 128-half row (64 data + 4 pad)
#define PC_SMEM (2 * 128 * PC_STR * 4)

__global__ __launch_bounds__(256, 2) void precompute_kernel(
    const float* __restrict__ emb)
{
    extern __shared__ char smem_raw[];
    uint32_t* As = (uint32_t*)smem_raw;                    // [128][PC_STR]
    uint32_t* Ws = As + 128 * PC_STR;                      // [128][PC_STR]

    const int tid  = threadIdx.x;
    const int warp = tid >> 5;
    const int lane = tid & 31;
    const int q    = lane & 3;
    const int lr   = lane >> 2;
    const int wm   = warp >> 2;
    const int wn   = warp & 3;
    const int row0 = blockIdx.x * 128;
    const int nblk = blockIdx.y;

    const int rj = tid & 15;       // 16B chunk within 256B row
    const int rr = tid >> 4;       // base row (16 rows per pass)

    #pragma unroll
    for (int pass = 0; pass < 8; pass++) {
        int r = pass * 16 + rr;
        int node = row0 + r;
        if (node >= NN) node = NN - 1;
        const float4* src = (const float4*)(emb + (size_t)node * HDIM + rj * 8);
        float4 a0 = src[0];
        float4 a1 = src[1];
        uint4 h;
        h.x = f2h2(a0.x, a0.y);
        h.y = f2h2(a0.z, a0.w);
        h.z = f2h2(a1.x, a1.y);
        h.w = f2h2(a1.z, a1.w);
        *(uint4*)(As + r * PC_STR + rj * 4) = h;

        uint4 v = *(const uint4*)(g_W1T + (size_t)(nblk * 128 + r) * 128 + rj * 8);
        *(uint4*)(Ws + r * PC_STR + rj * 4) = v;
    }
    __syncthreads();

    float acc[4][4][4];
    #pragma unroll
    for (int mt = 0; mt < 4; mt++)
        #pragma unroll
        for (int nt = 0; nt < 4; nt++)
            #pragma unroll
            for (int i = 0; i < 4; i++) acc[mt][nt][i] = 0.f;

    #pragma unroll
    for (int s = 0; s < 8; s++) {
        uint32_t bfr[4][2];
        #pragma unroll
        for (int nt = 0; nt < 4; nt++) {
            const uint32_t* bp = Ws + (wn * 32 + nt * 8 + lr) * PC_STR + q + 8 * s;
            bfr[nt][0] = bp[0];
            bfr[nt][1] = bp[4];
        }
        #pragma unroll
        for (int mt = 0; mt < 4; mt++) {
            const uint32_t* ap = As + (wm * 64 + mt * 16 + lr) * PC_STR + q + 8 * s;
            uint32_t a[4];
            a[0] = ap[0];
            a[1] = ap[8 * PC_STR];
            a[2] = ap[4];
            a[3] = ap[8 * PC_STR + 4];
            #pragma unroll
            for (int nt = 0; nt < 4; nt++)
                mma_f16(acc[mt][nt], a, bfr[nt]);
        }
    }

    #pragma unroll
    for (int mt = 0; mt < 4; mt++) {
        int n0 = row0 + wm * 64 + mt * 16 + lr;
        #pragma unroll
        for (int nt = 0; nt < 4; nt++) {
            int c = nblk * 128 + wn * 32 + nt * 8 + q * 2;
            if (n0 < NN)
                *(uint32_t*)(g_Ph + (size_t)n0 * 1024 + c) = f2h2(acc[mt][nt][0], acc[mt][nt][1]);
            if (n0 + 8 < NN)
                *(uint32_t*)(g_Ph + (size_t)(n0 + 8) * 1024 + c) = f2h2(acc[mt][nt][2], acc[mt][nt][3]);
        }
    }
}

// ============================================================================
// Kernel 2: edge MLP, cp.async 2-stage pipeline.
// Tile 128 edges x 128 N, K=512 in 8 chunks of 64.
// Raw P[col], P[row], W2T chunks staged; relu(pa+pb+b1) fused in A-frag load.
// ============================================================================
#define HS_STR 36                        // words per 64-half row
#define BUF_W  (128 * HS_STR)            // 4608 words per buffer
#define STG_W  (3 * BUF_W)               // 13824 words per stage
#define STG_B  (STG_W * 4)               // 55296 bytes
#define EK_SMEM (2 * STG_B + 1024 + 512 + 512 + 512 + 512)   // 113664

__global__ __launch_bounds__(256, 2) void edge_kernel(
    const int* __restrict__ ei,
    const float* __restrict__ b1,
    const float* __restrict__ b2, const float* __restrict__ W3,
    const float* __restrict__ b3, float* __restrict__ out)
{
    extern __shared__ char smem_raw[];
    uint32_t* pipe = (uint32_t*)smem_raw;                        // [2][STG_W]
    __half*   b1h  = (__half*)(smem_raw + 2 * STG_B);            // 512 halfs
    float*    b2s  = (float*)(smem_raw + 2 * STG_B + 1024);      // 128
    float*    w3s  = (float*)(smem_raw + 2 * STG_B + 1536);      // 128
    int*      colS = (int*)  (smem_raw + 2 * STG_B + 2048);      // 128
    int*      rowS = (int*)  (smem_raw + 2 * STG_B + 2560);      // 128
    float*    partS = (float*)smem_raw;                          // overlay (epilogue)

    const int tid  = threadIdx.x;
    const int warp = tid >> 5;
    const int lane = tid & 31;
    const int q    = lane & 3;
    const int lr   = lane >> 2;
    const int wm   = warp >> 2;
    const int wn   = warp & 3;
    const int e0   = blockIdx.x * 128;

    if (tid < 128) {
        int eg = e0 + tid;
        int c = 0, r = 0;
        if (eg < E_TOTAL) { c = ei[eg]; r = ei[E_TOTAL + eg]; }
        colS[tid] = c; rowS[tid] = r;
        b2s[tid] = b2[tid];
        w3s[tid] = W3[tid];
    }
    b1h[tid]       = __float2half_rn(b1[tid]);
    b1h[tid + 256] = __float2half_rn(b1[tid + 256]);
    __syncthreads();

    // per-thread gather plan: 8 threads x 16B cover one 128B row-chunk
    const int j   = tid & 7;
    const int e8  = tid >> 3;
    uint32_t paOff[4], pbOff[4], wOff[4], dPa[4], dPb[4], dW[4];
    const uint32_t smemBase = (uint32_t)__cvta_generic_to_shared(pipe);
    #pragma unroll
    for (int pass = 0; pass < 4; pass++) {
        int e = pass * 32 + e8;
        paOff[pass] = (uint32_t)colS[e] * 2048u + j * 16u;           // bytes into g_Ph
        pbOff[pass] = (uint32_t)rowS[e] * 2048u + 1024u + j * 16u;
        wOff[pass]  = (uint32_t)e * 1024u + j * 16u;                 // bytes into g_W2T
        uint32_t rw = (uint32_t)(e * HS_STR + j * 4) * 4u;           // byte offset in buffer
        dPa[pass] = smemBase + rw;
        dPb[pass] = smemBase + BUF_W * 4 + rw;
        dW[pass]  = smemBase + 2 * BUF_W * 4 + rw;
    }

    const char* gP = (const char*)g_Ph;
    const char* gW = (const char*)g_W2T;

    // prologue: issue stage for kc=0
    {
        #pragma unroll
        for (int pass = 0; pass < 4; pass++) {
            cp16(dPa[pass], gP + paOff[pass]);
            cp16(dPb[pass], gP + pbOff[pass]);
            cp16(dW[pass],  gW + wOff[pass]);
        }
        cp_commit();
    }

    float acc[4][4][4];
    #pragma unroll
    for (int mt = 0; mt < 4; mt++)
        #pragma unroll
        for (int nt = 0; nt < 4; nt++)
            #pragma unroll
            for (int i = 0; i < 4; i++) acc[mt][nt][i] = 0.f;

    const uint32_t* b1u = (const uint32_t*)b1h;
    const __half2 hz = __float2half2_rn(0.f);

    for (int kc = 0; kc < 8; kc++) {
        if (kc < 7) {
            uint32_t sb = ((kc + 1) & 1) * (uint32_t)STG_B;
            uint32_t kb = (uint32_t)(kc + 1) * 128u;
            #pragma unroll
            for (int pass = 0; pass < 4; pass++) {
                cp16(dPa[pass] + sb, gP + paOff[pass] + kb);
                cp16(dPb[pass] + sb, gP + pbOff[pass] + kb);
                cp16(dW[pass]  + sb, gW + wOff[pass]  + kb);
            }
            cp_commit();
            cp_wait<1>();
        } else {
            cp_wait<0>();
        }
        __syncthreads();

        const uint32_t* Pa = pipe + (kc & 1) * STG_W;
        const uint32_t* Pb = Pa + BUF_W;
        const uint32_t* Ws = Pa + 2 * BUF_W;

        #pragma unroll
        for (int s = 0; s < 4; s++) {
            __half2 b1lo = u2h2(b1u[kc * 32 + s * 8 + q]);
            __half2 b1hi = u2h2(b1u[kc * 32 + s * 8 + q + 4]);
            uint32_t bfr[4][2];
            #pragma unroll
            for (int nt = 0; nt < 4; nt++) {
                const uint32_t* bp = Ws + (wn * 32 + nt * 8 + lr) * HS_STR + q + 8 * s;
                bfr[nt][0] = bp[0];
                bfr[nt][1] = bp[4];
            }
            #pragma unroll
            for (int mt = 0; mt < 4; mt++) {
                int ro = (wm * 64 + mt * 16 + lr) * HS_STR + q + 8 * s;
                __half2 v0 = __hmax2(__hadd2(__hadd2(u2h2(Pa[ro]),              u2h2(Pb[ro])),              b1lo), hz);
                __half2 v1 = __hmax2(__hadd2(__hadd2(u2h2(Pa[ro + 8 * HS_STR]), u2h2(Pb[ro + 8 * HS_STR])), b1lo), hz);
                __half2 v2 = __hmax2(__hadd2(__hadd2(u2h2(Pa[ro + 4]),          u2h2(Pb[ro + 4])),          b1hi), hz);
                __half2 v3 = __hmax2(__hadd2(__hadd2(u2h2(Pa[ro + 8 * HS_STR + 4]), u2h2(Pb[ro + 8 * HS_STR + 4])), b1hi), hz);
                uint32_t a[4];
                a[0] = *(uint32_t*)&v0;
                a[1] = *(uint32_t*)&v1;
                a[2] = *(uint32_t*)&v2;
                a[3] = *(uint32_t*)&v3;
                #pragma unroll
                for (int nt = 0; nt < 4; nt++)
                    mma_f16(acc[mt][nt], a, bfr[nt]);
            }
        }
        __syncthreads();
    }

    // ---- epilogue: relu(+b2), partial dot with W3 per N-warp, block reduce ----
    #pragma unroll
    for (int mt = 0; mt < 4; mt++) {
        float p0 = 0.f, p1 = 0.f;
        #pragma unroll
        for (int nt = 0; nt < 4; nt++) {
            int n = wn * 32 + nt * 8 + q * 2;
            float w0 = w3s[n], w1 = w3s[n + 1];
            float g0 = b2s[n], g1 = b2s[n + 1];
            p0 += fmaxf(acc[mt][nt][0] + g0, 0.f) * w0 + fmaxf(acc[mt][nt][1] + g1, 0.f) * w1;
            p1 += fmaxf(acc[mt][nt][2] + g0, 0.f) * w0 + fmaxf(acc[mt][nt][3] + g1, 0.f) * w1;
        }
        p0 += __shfl_xor_sync(0xffffffffu, p0, 1);
        p0 += __shfl_xor_sync(0xffffffffu, p0, 2);
        p1 += __shfl_xor_sync(0xffffffffu, p1, 1);
        p1 += __shfl_xor_sync(0xffffffffu, p1, 2);
        if (q == 0) {
            int rl = wm * 64 + mt * 16 + lr;
            partS[wn * 128 + rl]     = p0;
            partS[wn * 128 + rl + 8] = p1;
        }
    }
    __syncthreads();
    if (tid < 128) {
        float s = partS[tid] + partS[128 + tid] + partS[256 + tid] + partS[384 + tid] + b3[0];
        int eg = e0 + tid;
        if (eg < E_TOTAL) out[eg] = 1.f / (1.f + expf(-s));
    }
}

// ============================================================================
extern "C" void kernel_launch(void* const* d_in, const int* in_sizes, int n_in,
                              void* d_out, int out_size)
{
    const float* emb = (const float*)d_in[0];
    const int*   ei  = (const int*)d_in[1];
    const float* W1  = (const float*)d_in[2];
    const float* b1  = (const float*)d_in[3];
    const float* W2  = (const float*)d_in[4];
    const float* b2  = (const float*)d_in[5];
    const float* W3  = (const float*)d_in[6];
    const float* b3  = (const float*)d_in[7];
    float* out = (float*)d_out;

    cudaFuncSetAttribute(precompute_kernel,
                         cudaFuncAttributeMaxDynamicSharedMemorySize, PC_SMEM);
    cudaFuncSetAttribute(edge_kernel,
                         cudaFuncAttributeMaxDynamicSharedMemorySize, EK_SMEM);

    prep_kernel<<<768, 256>>>(W1, W2);
    precompute_kernel<<<dim3(782, 8), 256, PC_SMEM>>>(emb);
    edge_kernel<<<7813, 256, EK_SMEM>>>(ei, b1, b2, W3, b3, out);
}

// round 6
// speedup vs baseline: 3.8414x; 1.1489x over previous
#include <cuda_runtime.h>
#include <cuda_fp16.h>
#include <cstdint>

#define E_TOTAL  1000000
#define NN       100000
#define HDIM     128

// P = emb @ [W1_top | W1_bot] (+b1 folded into cols 0..511), fp16 : [NN][1024]
__device__ __half g_Ph[(size_t)NN * 1024];
// W1 transposed fp16 : [1024 n][128 k]
__device__ __half g_W1T[(size_t)1024 * 128];
// W2 transposed fp16 : [128 n][512 k]
__device__ __half g_W2T[(size_t)128 * 512];

__device__ __forceinline__ void mma_f16(float* d, const uint32_t* a, const uint32_t* b) {
    asm volatile(
        "mma.sync.aligned.m16n8k16.row.col.f32.f16.f16.f32 "
        "{%0,%1,%2,%3}, {%4,%5,%6,%7}, {%8,%9}, {%0,%1,%2,%3};\n"
        : "+f"(d[0]), "+f"(d[1]), "+f"(d[2]), "+f"(d[3])
        : "r"(a[0]), "r"(a[1]), "r"(a[2]), "r"(a[3]),
          "r"(b[0]), "r"(b[1]));
}
__device__ __forceinline__ uint32_t f2h2(float lo, float hi) {
    __half2 p = __floats2half2_rn(lo, hi);
    return *reinterpret_cast<uint32_t*>(&p);
}
__device__ __forceinline__ uint32_t addrelu(uint32_t a, uint32_t b) {
    __half2 s = __hmax2(__hadd2(*reinterpret_cast<__half2*>(&a),
                                *reinterpret_cast<__half2*>(&b)),
                        __float2half2_rn(0.f));
    return *reinterpret_cast<uint32_t*>(&s);
}
__device__ __forceinline__ void cp16(uint32_t s, const void* g) {
    asm volatile("cp.async.cg.shared.global [%0], [%1], 16;\n" :: "r"(s), "l"(g));
}
__device__ __forceinline__ void cp_commit() {
    asm volatile("cp.async.commit_group;\n");
}
template <int N>
__device__ __forceinline__ void cp_wait() {
    asm volatile("cp.async.wait_group %0;\n" :: "n"(N));
}
__device__ __forceinline__ uint32_t smem_u32(const void* p) {
    uint32_t a;
    asm("{ .reg .u64 t; cvta.to.shared.u64 t, %1; cvt.u32.u64 %0, t; }" : "=r"(a) : "l"(p));
    return a;
}

// ============================================================================
// Kernel 0: prep — W1 -> g_W1T fp16 [1024][128]; W2 -> g_W2T fp16 [128][512]
// ============================================================================
__global__ __launch_bounds__(256) void prep_kernel(
    const float* __restrict__ W1, const float* __restrict__ W2)
{
    int bid = blockIdx.x;
    int tid = threadIdx.x;
    if (bid < 512) {
        int idx = bid * 256 + tid;
        int k = idx >> 10;
        int n = idx & 1023;
        float v = (n < 512) ? W1[(size_t)k * 512 + n]
                            : W1[(size_t)(128 + k) * 512 + (n - 512)];
        g_W1T[(size_t)n * 128 + k] = __float2half_rn(v);
    } else {
        int idx = (bid - 512) * 256 + tid;
        int k = idx >> 7;
        int n = idx & 127;
        g_W2T[(size_t)n * 512 + k] = __float2half_rn(W2[(size_t)k * 128 + n]);
    }
}

// ============================================================================
// Kernel 1: P = emb @ Wcat (+ b1 on cols<512) -> fp16. Tile 128x128, K=128.
// ============================================================================
#define PC_STR 68
#define PC_SMEM (2 * 128 * PC_STR * 4)

__global__ __launch_bounds__(256, 2) void precompute_kernel(
    const float* __restrict__ emb, const float* __restrict__ b1)
{
    extern __shared__ char smem_raw[];
    uint32_t* As = (uint32_t*)smem_raw;
    uint32_t* Ws = As + 128 * PC_STR;

    const int tid  = threadIdx.x;
    const int warp = tid >> 5;
    const int lane = tid & 31;
    const int q    = lane & 3;
    const int lr   = lane >> 2;
    const int wm   = warp >> 2;
    const int wn   = warp & 3;
    const int row0 = blockIdx.x * 128;
    const int nblk = blockIdx.y;

    const int rj = tid & 15;
    const int rr = tid >> 4;

    #pragma unroll
    for (int pass = 0; pass < 8; pass++) {
        int r = pass * 16 + rr;
        int node = row0 + r;
        if (node >= NN) node = NN - 1;
        const float4* src = (const float4*)(emb + (size_t)node * HDIM + rj * 8);
        float4 a0 = src[0];
        float4 a1 = src[1];
        uint4 h;
        h.x = f2h2(a0.x, a0.y);
        h.y = f2h2(a0.z, a0.w);
        h.z = f2h2(a1.x, a1.y);
        h.w = f2h2(a1.z, a1.w);
        *(uint4*)(As + r * PC_STR + rj * 4) = h;

        uint4 v = *(const uint4*)(g_W1T + (size_t)(nblk * 128 + r) * 128 + rj * 8);
        *(uint4*)(Ws + r * PC_STR + rj * 4) = v;
    }
    __syncthreads();

    float acc[4][4][4];
    #pragma unroll
    for (int mt = 0; mt < 4; mt++)
        #pragma unroll
        for (int nt = 0; nt < 4; nt++)
            #pragma unroll
            for (int i = 0; i < 4; i++) acc[mt][nt][i] = 0.f;

    #pragma unroll
    for (int s = 0; s < 8; s++) {
        uint32_t bfr[4][2];
        #pragma unroll
        for (int nt = 0; nt < 4; nt++) {
            const uint32_t* bp = Ws + (wn * 32 + nt * 8 + lr) * PC_STR + q + 8 * s;
            bfr[nt][0] = bp[0];
            bfr[nt][1] = bp[4];
        }
        #pragma unroll
        for (int mt = 0; mt < 4; mt++) {
            const uint32_t* ap = As + (wm * 64 + mt * 16 + lr) * PC_STR + q + 8 * s;
            uint32_t a[4];
            a[0] = ap[0];
            a[1] = ap[8 * PC_STR];
            a[2] = ap[4];
            a[3] = ap[8 * PC_STR + 4];
            #pragma unroll
            for (int nt = 0; nt < 4; nt++)
                mma_f16(acc[mt][nt], a, bfr[nt]);
        }
    }

    const bool bias = (nblk < 4);
    #pragma unroll
    for (int mt = 0; mt < 4; mt++) {
        int n0 = row0 + wm * 64 + mt * 16 + lr;
        #pragma unroll
        for (int nt = 0; nt < 4; nt++) {
            int c = nblk * 128 + wn * 32 + nt * 8 + q * 2;
            float a0 = acc[mt][nt][0], a1 = acc[mt][nt][1];
            float a2 = acc[mt][nt][2], a3 = acc[mt][nt][3];
            if (bias) {
                float u = b1[c], v = b1[c + 1];
                a0 += u; a1 += v; a2 += u; a3 += v;
            }
            if (n0 < NN)
                *(uint32_t*)(g_Ph + (size_t)n0 * 1024 + c) = f2h2(a0, a1);
            if (n0 + 8 < NN)
                *(uint32_t*)(g_Ph + (size_t)(n0 + 8) * 1024 + c) = f2h2(a2, a3);
        }
    }
}

// ============================================================================
// Kernel 2: edge MLP, 128 threads (4 warps as 2M x 2N), warp tile 64x64.
// Tile 128 edges x 128 N, K=512 in 8 chunks of 64; cp.async 2-stage pipeline;
// relu(Pa+Pb) fused into the A-fragment load (b1 folded into P).
// ============================================================================
#define HS_STR 36                        // uint32 words per 64-half row
#define BUF_W  (128 * HS_STR)            // 4608 words per buffer
#define STG_W  (3 * BUF_W)               // Pa | Pb | W2
#define STG_B  (STG_W * 4)               // 55296 bytes
#define EK_SMEM (2 * STG_B + 3072)

__global__ __launch_bounds__(128, 2) void edge_kernel(
    const int* __restrict__ ei,
    const float* __restrict__ b2, const float* __restrict__ W3,
    const float* __restrict__ b3, float* __restrict__ out)
{
    extern __shared__ char smem_raw[];
    uint32_t* pipe = (uint32_t*)smem_raw;                    // [2][STG_W]
    float* b2s  = (float*)(smem_raw + 2 * STG_B);            // 128
    float* w3s  = (float*)(smem_raw + 2 * STG_B + 512);      // 128
    int*   colS = (int*)  (smem_raw + 2 * STG_B + 1024);     // 128
    int*   rowS = (int*)  (smem_raw + 2 * STG_B + 1536);     // 128
    float* partS = (float*)(smem_raw + 2 * STG_B + 2048);    // 256

    const int tid  = threadIdx.x;
    const int warp = tid >> 5;
    const int lane = tid & 31;
    const int q    = lane & 3;
    const int lr   = lane >> 2;
    const int wy   = warp >> 1;          // 0..1 : M group (64 edges)
    const int wx   = warp & 1;           // 0..1 : N group (64 cols)
    const int e0   = blockIdx.x * 128;

    {
        int eg = e0 + tid;
        int c = 0, r = 0;
        if (eg < E_TOTAL) { c = ei[eg]; r = ei[E_TOTAL + eg]; }
        colS[tid] = c; rowS[tid] = r;
        b2s[tid] = b2[tid];
        w3s[tid] = W3[tid];
    }
    __syncthreads();

    // staging plan: 8 threads x 16B cover one 128B row-chunk; 8 passes x 16 rows
    const int j   = tid & 7;
    const int e16 = tid >> 3;            // 0..15
    const uint32_t smemBase = smem_u32(pipe);
    uint32_t paOff[8], pbOff[8];
    uint32_t dPa[8], dPb[8], dW[8], wOff[8];
    #pragma unroll
    for (int p = 0; p < 8; p++) {
        int e = p * 16 + e16;
        paOff[p] = (uint32_t)colS[e] * 2048u + j * 16u;
        pbOff[p] = (uint32_t)rowS[e] * 2048u + 1024u + j * 16u;
        wOff[p]  = (uint32_t)e * 1024u + j * 16u;
        uint32_t rw = (uint32_t)(e * HS_STR + j * 4) * 4u;
        dPa[p] = smemBase + rw;
        dPb[p] = smemBase + BUF_W * 4 + rw;
        dW[p]  = smemBase + 2 * BUF_W * 4 + rw;
    }
    const char* gP = (const char*)g_Ph;
    const char* gW = (const char*)g_W2T;

    // prologue: stage chunk 0
    #pragma unroll
    for (int p = 0; p < 8; p++) {
        cp16(dPa[p], gP + paOff[p]);
        cp16(dPb[p], gP + pbOff[p]);
        cp16(dW[p],  gW + wOff[p]);
    }
    cp_commit();

    float acc[4][8][4];
    #pragma unroll
    for (int mt = 0; mt < 4; mt++)
        #pragma unroll
        for (int nt = 0; nt < 8; nt++)
            #pragma unroll
            for (int i = 0; i < 4; i++) acc[mt][nt][i] = 0.f;

    for (int kc = 0; kc < 8; kc++) {
        if (kc < 7) {
            uint32_t sb = ((kc + 1) & 1) * (uint32_t)STG_B;
            uint32_t kb = (uint32_t)(kc + 1) * 128u;
            #pragma unroll
            for (int p = 0; p < 8; p++) {
                cp16(dPa[p] + sb, gP + paOff[p] + kb);
                cp16(dPb[p] + sb, gP + pbOff[p] + kb);
                cp16(dW[p]  + sb, gW + wOff[p]  + kb);
            }
            cp_commit();
            cp_wait<1>();
        } else {
            cp_wait<0>();
        }
        __syncthreads();

        const uint32_t* Pa = pipe + (kc & 1) * STG_W;
        const uint32_t* Pb = Pa + BUF_W;
        const uint32_t* Ws = Pa + 2 * BUF_W;

        #pragma unroll
        for (int s = 0; s < 4; s++) {
            uint32_t bfr[8][2];
            #pragma unroll
            for (int nt = 0; nt < 8; nt++) {
                const uint32_t* bp = Ws + (wx * 64 + nt * 8 + lr) * HS_STR + q + 8 * s;
                bfr[nt][0] = bp[0];
                bfr[nt][1] = bp[4];
            }
            #pragma unroll
            for (int mt = 0; mt < 4; mt++) {
                int ro = (wy * 64 + mt * 16 + lr) * HS_STR + q + 8 * s;
                uint32_t a[4];
                a[0] = addrelu(Pa[ro],                  Pb[ro]);
                a[1] = addrelu(Pa[ro + 8 * HS_STR],     Pb[ro + 8 * HS_STR]);
                a[2] = addrelu(Pa[ro + 4],              Pb[ro + 4]);
                a[3] = addrelu(Pa[ro + 8 * HS_STR + 4], Pb[ro + 8 * HS_STR + 4]);
                #pragma unroll
                for (int nt = 0; nt < 8; nt++)
                    mma_f16(acc[mt][nt], a, bfr[nt]);
            }
        }
        __syncthreads();
    }

    // ---- epilogue: relu(+b2), partial dot with W3 per N-warp-group, reduce ----
    #pragma unroll
    for (int mt = 0; mt < 4; mt++) {
        float p0 = 0.f, p1 = 0.f;
        #pragma unroll
        for (int nt = 0; nt < 8; nt++) {
            int n = wx * 64 + nt * 8 + q * 2;
            float w0 = w3s[n], w1 = w3s[n + 1];
            float g0 = b2s[n], g1 = b2s[n + 1];
            p0 += fmaxf(acc[mt][nt][0] + g0, 0.f) * w0 + fmaxf(acc[mt][nt][1] + g1, 0.f) * w1;
            p1 += fmaxf(acc[mt][nt][2] + g0, 0.f) * w0 + fmaxf(acc[mt][nt][3] + g1, 0.f) * w1;
        }
        p0 += __shfl_xor_sync(0xffffffffu, p0, 1);
        p0 += __shfl_xor_sync(0xffffffffu, p0, 2);
        p1 += __shfl_xor_sync(0xffffffffu, p1, 1);
        p1 += __shfl_xor_sync(0xffffffffu, p1, 2);
        if (q == 0) {
            int rl = wy * 64 + mt * 16 + lr;
            partS[wx * 128 + rl]     = p0;
            partS[wx * 128 + rl + 8] = p1;
        }
    }
    __syncthreads();
    {
        float s = partS[tid] + partS[128 + tid] + b3[0];
        int eg = e0 + tid;
        if (eg < E_TOTAL) out[eg] = 1.f / (1.f + expf(-s));
    }
}

// ============================================================================
extern "C" void kernel_launch(void* const* d_in, const int* in_sizes, int n_in,
                              void* d_out, int out_size)
{
    const float* emb = (const float*)d_in[0];
    const int*   ei  = (const int*)d_in[1];
    const float* W1  = (const float*)d_in[2];
    const float* b1  = (const float*)d_in[3];
    const float* W2  = (const float*)d_in[4];
    const float* b2  = (const float*)d_in[5];
    const float* W3  = (const float*)d_in[6];
    const float* b3  = (const float*)d_in[7];
    float* out = (float*)d_out;

    cudaFuncSetAttribute(precompute_kernel,
                         cudaFuncAttributeMaxDynamicSharedMemorySize, PC_SMEM);
    cudaFuncSetAttribute(edge_kernel,
                         cudaFuncAttributeMaxDynamicSharedMemorySize, EK_SMEM);

    prep_kernel<<<768, 256>>>(W1, W2);
    precompute_kernel<<<dim3(782, 8), 256, PC_SMEM>>>(emb, b1);
    edge_kernel<<<7813, 128, EK_SMEM>>>(ei, b2, W3, b3, out);
}